// round 3
// baseline (speedup 1.0000x reference)
#include <cuda_runtime.h>
#include <math.h>

#define BB 64
#define LL 256
#define DIN 55
#define AH 32
#define AC 8
#define CC 64
#define GG 192
#define HH 64
#define SIGW 4160   // CC + CC*CC

// Scratch (device globals — no runtime allocation allowed)
__device__ float g_P[(size_t)BB * CC * LL];        // p in [b][c][t] layout, 4 MB
__device__ float g_R[(size_t)BB * LL * GG];        // per-step projection increments, 12.6 MB
__device__ float g_H0[(size_t)BB * LL * HH];       // layer-0 hidden sequence, 4 MB

// ---------------------------------------------------------------------------
// Kernel A: Augment. p = concat(x, time, relu(x W1^T + b1) W2^T + b2)
// One block per batch element, one thread per timestep.
// ---------------------------------------------------------------------------
__global__ void __launch_bounds__(LL) augment_kernel(
    const float* __restrict__ x,
    const float* __restrict__ w1, const float* __restrict__ b1,
    const float* __restrict__ w2, const float* __restrict__ b2)
{
    __shared__ float w1s[AH * DIN];
    __shared__ float w2s[AC * AH];
    __shared__ float b1s[AH];
    __shared__ float b2s[AC];

    int b = blockIdx.x;
    int t = threadIdx.x;

    for (int i = threadIdx.x; i < AH * DIN; i += blockDim.x) w1s[i] = w1[i];
    for (int i = threadIdx.x; i < AC * AH; i += blockDim.x)  w2s[i] = w2[i];
    if (threadIdx.x < AH) b1s[threadIdx.x] = b1[threadIdx.x];
    if (threadIdx.x < AC) b2s[threadIdx.x] = b2[threadIdx.x];
    __syncthreads();

    float xv[DIN];
    const float* xp = x + ((size_t)b * LL + t) * DIN;
#pragma unroll
    for (int c = 0; c < DIN; c++) xv[c] = xp[c];

    float hb[AH];
#pragma unroll
    for (int h = 0; h < AH; h++) {
        float acc = b1s[h];
#pragma unroll
        for (int c = 0; c < DIN; c++) acc += w1s[h * DIN + c] * xv[c];
        hb[h] = fmaxf(acc, 0.0f);
    }

    float* Pp = g_P + (size_t)b * CC * LL + t;   // [b][c][t]: stride LL per channel
#pragma unroll
    for (int c = 0; c < DIN; c++) Pp[(size_t)c * LL] = xv[c];
    Pp[(size_t)DIN * LL] = (float)t / (float)(LL - 1);
#pragma unroll
    for (int a = 0; a < AC; a++) {
        float acc = b2s[a];
#pragma unroll
        for (int h = 0; h < AH; h++) acc += w2s[a * AH + h] * hb[h];
        Pp[(size_t)(DIN + 1 + a) * LL] = acc;
    }
}

// ---------------------------------------------------------------------------
// Kernel B: r[b,t,g] = Wih0[g, 0:64] . d[t]  +  sum_ij Wih0[g, 64+64i+j] a_i d_j
// GEMM with generated B-matrix. Block tile: 64 gates x 64 positions.
// Grid: (LL/64 time tiles, GG/64 gate tiles, BB batch).
// ---------------------------------------------------------------------------
__global__ void __launch_bounds__(256, 1) siggemm_kernel(const float* __restrict__ Wih0)
{
    __shared__ float a_s[CC][64];
    __shared__ float d_s[CC][64];
    __shared__ float W_s[64][64];

    const int t0    = blockIdx.x * 64;
    const int gbase = blockIdx.y * 64;
    const int b     = blockIdx.z;
    const int tid   = threadIdx.x;
    const int gi    = tid >> 4;    // 0..15 -> gates gi*4 .. gi*4+3
    const int pi    = tid & 15;    // 0..15 -> positions pi*4 .. pi*4+3

    // Load a/d tiles: d = p[t]-p[t-1], a = (p[t]+p[t-1])/2 (p[-1] = 0)
    for (int l = tid; l < CC * 64; l += 256) {
        int c  = l >> 6;
        int tt = l & 63;
        int t  = t0 + tt;
        const float* Pc = g_P + ((size_t)b * CC + c) * LL;
        float cur  = Pc[t];
        float prev = (t == 0) ? 0.0f : Pc[t - 1];
        d_s[c][tt] = cur - prev;
        a_s[c][tt] = 0.5f * (cur + prev);
    }

    float acc[4][4];
#pragma unroll
    for (int g = 0; g < 4; g++)
#pragma unroll
        for (int p = 0; p < 4; p++) acc[g][p] = 0.0f;

    // K loop: i = -1 is the level-1 (dx) part, i >= 0 the rank-1 outer chunks
    for (int i = -1; i < CC; i++) {
        __syncthreads();
        int koff = (i < 0) ? 0 : (CC + i * CC);
        for (int l = tid; l < 64 * 64; l += 256) {
            int g = l >> 6;
            int j = l & 63;
            W_s[g][j] = Wih0[(size_t)(gbase + g) * SIGW + koff + j];
        }
        __syncthreads();

        float4 av;
        if (i < 0) av = make_float4(1.0f, 1.0f, 1.0f, 1.0f);
        else       av = *(const float4*)&a_s[i][pi * 4];

#pragma unroll
        for (int j0 = 0; j0 < 64; j0 += 4) {
            float4 wv[4];
#pragma unroll
            for (int g = 0; g < 4; g++)
                wv[g] = *(const float4*)&W_s[gi * 4 + g][j0];
#pragma unroll
            for (int jj = 0; jj < 4; jj++) {
                float4 dv = *(const float4*)&d_s[j0 + jj][pi * 4];
                float b0 = av.x * dv.x;
                float b1 = av.y * dv.y;
                float b2 = av.z * dv.z;
                float b3 = av.w * dv.w;
#pragma unroll
                for (int g = 0; g < 4; g++) {
                    float w = (jj == 0) ? wv[g].x : (jj == 1) ? wv[g].y
                            : (jj == 2) ? wv[g].z : wv[g].w;
                    acc[g][0] += w * b0;
                    acc[g][1] += w * b1;
                    acc[g][2] += w * b2;
                    acc[g][3] += w * b3;
                }
            }
        }
    }

    // Write r: [b][t][g] layout, float4 over 4 consecutive gates
#pragma unroll
    for (int p = 0; p < 4; p++) {
        int t = t0 + pi * 4 + p;
        float4 v = make_float4(acc[0][p], acc[1][p], acc[2][p], acc[3][p]);
        *(float4*)(g_R + ((size_t)b * LL + t) * GG + gbase + gi * 4) = v;
    }
}

// ---------------------------------------------------------------------------
// Kernel C0: layer-0 GRU scan. One block per batch element, thread g = gate g.
// Folds the cumsum of r into the scan. Whh0 row in registers.
// Writes h0 sequence to g_H0.
// ---------------------------------------------------------------------------
__device__ __forceinline__ float sigm(float v) { return 1.0f / (1.0f + expf(-v)); }

__global__ void __launch_bounds__(GG, 1) gru0_kernel(
    const float* __restrict__ Whh0, const float* __restrict__ bih0,
    const float* __restrict__ bhh0)
{
    __shared__ float s_xg[GG];
    __shared__ float s_gh[GG];
    __shared__ float h0s[HH];

    const int b = blockIdx.x;
    const int g = threadIdx.x;

    float w0r[HH];
#pragma unroll
    for (int k = 0; k < HH; k++) w0r[k] = Whh0[g * HH + k];

    float acc   = bih0[g];       // running cumsum -> xg0[t]
    float bhh0r = bhh0[g];

    if (g < HH) h0s[g] = 0.0f;
    __syncthreads();

    const float* rptr = g_R + (size_t)b * LL * GG + g;
    float* hout = g_H0 + (size_t)b * LL * HH;
    float rv_next = rptr[0];

    for (int t = 0; t < LL; t++) {
        float rv = rv_next;
        if (t + 1 < LL) rv_next = rptr[(size_t)(t + 1) * GG];   // prefetch next step
        acc += rv;

        float gh = bhh0r;
#pragma unroll
        for (int k = 0; k < HH; k += 4) {
            float4 h4 = *(const float4*)&h0s[k];
            gh += w0r[k] * h4.x + w0r[k + 1] * h4.y + w0r[k + 2] * h4.z + w0r[k + 3] * h4.w;
        }
        s_xg[g] = acc;
        s_gh[g] = gh;
        __syncthreads();

        if (g < HH) {
            float r = sigm(s_xg[g] + s_gh[g]);
            float z = sigm(s_xg[HH + g] + s_gh[HH + g]);
            float n = tanhf(s_xg[2 * HH + g] + r * s_gh[2 * HH + g]);
            float hn = (1.0f - z) * n + z * h0s[g];
            h0s[g] = hn;
            hout[(size_t)t * HH + g] = hn;
        }
        __syncthreads();
    }
}

// ---------------------------------------------------------------------------
// Kernel C1: layer-1 GRU scan. Wih1 row + Whh1 row in registers (128 regs).
// Reads h0 sequence from g_H0 (L2-resident), writes final output.
// ---------------------------------------------------------------------------
__global__ void __launch_bounds__(GG, 1) gru1_kernel(
    const float* __restrict__ Wih1, const float* __restrict__ Whh1,
    const float* __restrict__ bih1, const float* __restrict__ bhh1,
    float* __restrict__ out)
{
    __shared__ float s_xg[GG];
    __shared__ float s_gh[GG];
    __shared__ float h0s[HH];
    __shared__ float h1s[HH];

    const int b = blockIdx.x;
    const int g = threadIdx.x;

    float wir[HH], whr[HH];
#pragma unroll
    for (int k = 0; k < HH; k++) wir[k] = Wih1[g * HH + k];
#pragma unroll
    for (int k = 0; k < HH; k++) whr[k] = Whh1[g * HH + k];

    float bih1r = bih1[g];
    float bhh1r = bhh1[g];

    if (g < HH) h1s[g] = 0.0f;
    __syncthreads();

    const float* hin = g_H0 + (size_t)b * LL * HH;

    for (int t = 0; t < LL; t++) {
        if (g < HH) h0s[g] = hin[(size_t)t * HH + g];
        __syncthreads();

        float xg = bih1r;
        float gh = bhh1r;
#pragma unroll
        for (int k = 0; k < HH; k += 4) {
            float4 h04 = *(const float4*)&h0s[k];
            float4 h14 = *(const float4*)&h1s[k];
            xg += wir[k] * h04.x + wir[k + 1] * h04.y + wir[k + 2] * h04.z + wir[k + 3] * h04.w;
            gh += whr[k] * h14.x + whr[k + 1] * h14.y + whr[k + 2] * h14.z + whr[k + 3] * h14.w;
        }
        s_xg[g] = xg;
        s_gh[g] = gh;
        __syncthreads();

        if (g < HH) {
            float r = sigm(s_xg[g] + s_gh[g]);
            float z = sigm(s_xg[HH + g] + s_gh[HH + g]);
            float n = tanhf(s_xg[2 * HH + g] + r * s_gh[2 * HH + g]);
            float hn = (1.0f - z) * n + z * h1s[g];
            h1s[g] = hn;
            out[((size_t)b * LL + t) * HH + g] = hn;
        }
        __syncthreads();
    }
}

// ---------------------------------------------------------------------------
extern "C" void kernel_launch(void* const* d_in, const int* in_sizes, int n_in,
                              void* d_out, int out_size)
{
    const float* x    = (const float*)d_in[0];
    const float* cw1  = (const float*)d_in[1];
    const float* cb1  = (const float*)d_in[2];
    const float* cw2  = (const float*)d_in[3];
    const float* cb2  = (const float*)d_in[4];
    const float* Wih0 = (const float*)d_in[5];
    const float* Whh0 = (const float*)d_in[6];
    const float* bih0 = (const float*)d_in[7];
    const float* bhh0 = (const float*)d_in[8];
    const float* Wih1 = (const float*)d_in[9];
    const float* Whh1 = (const float*)d_in[10];
    const float* bih1 = (const float*)d_in[11];
    const float* bhh1 = (const float*)d_in[12];
    float* out = (float*)d_out;

    augment_kernel<<<BB, LL>>>(x, cw1, cb1, cw2, cb2);

    dim3 gridB(LL / 64, GG / 64, BB);
    siggemm_kernel<<<gridB, 256>>>(Wih0);

    gru0_kernel<<<BB, GG>>>(Whh0, bih0, bhh0);
    gru1_kernel<<<BB, GG>>>(Wih1, Whh1, bih1, bhh1, out);
}

// round 4
// speedup vs baseline: 1.0851x; 1.0851x over previous
#include <cuda_runtime.h>
#include <math.h>

#define BB 64
#define LL 256
#define DIN 55
#define AH 32
#define AC 8
#define CC 64
#define GG 192
#define HH 64
#define SIGW 4160   // CC + CC*CC

// Scratch (device globals — no runtime allocation allowed)
__device__ float g_P[(size_t)BB * CC * LL];        // p in [b][c][t] layout, 4 MB
__device__ float g_R[(size_t)BB * LL * GG];        // per-step projection increments, 12.6 MB
__device__ float g_H0[(size_t)BB * LL * HH];       // layer-0 hidden sequence, 4 MB

// ---------------------------------------------------------------------------
// Kernel A: Augment. p = concat(x, time, relu(x W1^T + b1) W2^T + b2)
// ---------------------------------------------------------------------------
__global__ void __launch_bounds__(LL) augment_kernel(
    const float* __restrict__ x,
    const float* __restrict__ w1, const float* __restrict__ b1,
    const float* __restrict__ w2, const float* __restrict__ b2)
{
    __shared__ float w1s[AH * DIN];
    __shared__ float w2s[AC * AH];
    __shared__ float b1s[AH];
    __shared__ float b2s[AC];

    int b = blockIdx.x;
    int t = threadIdx.x;

    for (int i = threadIdx.x; i < AH * DIN; i += blockDim.x) w1s[i] = w1[i];
    for (int i = threadIdx.x; i < AC * AH; i += blockDim.x)  w2s[i] = w2[i];
    if (threadIdx.x < AH) b1s[threadIdx.x] = b1[threadIdx.x];
    if (threadIdx.x < AC) b2s[threadIdx.x] = b2[threadIdx.x];
    __syncthreads();

    float xv[DIN];
    const float* xp = x + ((size_t)b * LL + t) * DIN;
#pragma unroll
    for (int c = 0; c < DIN; c++) xv[c] = xp[c];

    float hb[AH];
#pragma unroll
    for (int h = 0; h < AH; h++) {
        float acc = b1s[h];
#pragma unroll
        for (int c = 0; c < DIN; c++) acc += w1s[h * DIN + c] * xv[c];
        hb[h] = fmaxf(acc, 0.0f);
    }

    float* Pp = g_P + (size_t)b * CC * LL + t;   // [b][c][t]: stride LL per channel
#pragma unroll
    for (int c = 0; c < DIN; c++) Pp[(size_t)c * LL] = xv[c];
    Pp[(size_t)DIN * LL] = (float)t / (float)(LL - 1);
#pragma unroll
    for (int a = 0; a < AC; a++) {
        float acc = b2s[a];
#pragma unroll
        for (int h = 0; h < AH; h++) acc += w2s[a * AH + h] * hb[h];
        Pp[(size_t)(DIN + 1 + a) * LL] = acc;
    }
}

// ---------------------------------------------------------------------------
// Kernel B: r[b,t,g] = Wih0[g, 0:64] . d[t]  +  sum_ij Wih0[g, 64+64i+j] a_i d_j
// ---------------------------------------------------------------------------
__global__ void __launch_bounds__(256, 1) siggemm_kernel(const float* __restrict__ Wih0)
{
    __shared__ float a_s[CC][64];
    __shared__ float d_s[CC][64];
    __shared__ float W_s[64][64];

    const int t0    = blockIdx.x * 64;
    const int gbase = blockIdx.y * 64;
    const int b     = blockIdx.z;
    const int tid   = threadIdx.x;
    const int gi    = tid >> 4;
    const int pi    = tid & 15;

    for (int l = tid; l < CC * 64; l += 256) {
        int c  = l >> 6;
        int tt = l & 63;
        int t  = t0 + tt;
        const float* Pc = g_P + ((size_t)b * CC + c) * LL;
        float cur  = Pc[t];
        float prev = (t == 0) ? 0.0f : Pc[t - 1];
        d_s[c][tt] = cur - prev;
        a_s[c][tt] = 0.5f * (cur + prev);
    }

    float acc[4][4];
#pragma unroll
    for (int g = 0; g < 4; g++)
#pragma unroll
        for (int p = 0; p < 4; p++) acc[g][p] = 0.0f;

    for (int i = -1; i < CC; i++) {
        __syncthreads();
        int koff = (i < 0) ? 0 : (CC + i * CC);
        for (int l = tid; l < 64 * 64; l += 256) {
            int g = l >> 6;
            int j = l & 63;
            W_s[g][j] = Wih0[(size_t)(gbase + g) * SIGW + koff + j];
        }
        __syncthreads();

        float4 av;
        if (i < 0) av = make_float4(1.0f, 1.0f, 1.0f, 1.0f);
        else       av = *(const float4*)&a_s[i][pi * 4];

#pragma unroll
        for (int j0 = 0; j0 < 64; j0 += 4) {
            float4 wv[4];
#pragma unroll
            for (int g = 0; g < 4; g++)
                wv[g] = *(const float4*)&W_s[gi * 4 + g][j0];
#pragma unroll
            for (int jj = 0; jj < 4; jj++) {
                float4 dv = *(const float4*)&d_s[j0 + jj][pi * 4];
                float b0 = av.x * dv.x;
                float b1 = av.y * dv.y;
                float b2 = av.z * dv.z;
                float b3 = av.w * dv.w;
#pragma unroll
                for (int g = 0; g < 4; g++) {
                    float w = (jj == 0) ? wv[g].x : (jj == 1) ? wv[g].y
                            : (jj == 2) ? wv[g].z : wv[g].w;
                    acc[g][0] += w * b0;
                    acc[g][1] += w * b1;
                    acc[g][2] += w * b2;
                    acc[g][3] += w * b3;
                }
            }
        }
    }

#pragma unroll
    for (int p = 0; p < 4; p++) {
        int t = t0 + pi * 4 + p;
        float4 v = make_float4(acc[0][p], acc[1][p], acc[2][p], acc[3][p]);
        *(float4*)(g_R + ((size_t)b * LL + t) * GG + gbase + gi * 4) = v;
    }
}

// ---------------------------------------------------------------------------
// Fast activations: __expf (MUFU ex2) + approximate division.
// tanh clamped at |v|<=10 to avoid inf/inf (tanh(10)=1-4e-9, below fp32 eps).
// ---------------------------------------------------------------------------
__device__ __forceinline__ float fast_sigm(float v) {
    return __fdividef(1.0f, 1.0f + __expf(-v));
}
__device__ __forceinline__ float fast_tanh(float v) {
    v = fminf(fmaxf(v, -10.0f), 10.0f);
    float e = __expf(2.0f * v);
    return __fdividef(e - 1.0f, e + 1.0f);
}

// 64-length dot product against smem vector with 4 independent accumulators.
__device__ __forceinline__ float dot64(const float* __restrict__ w,
                                       const float* __restrict__ hs) {
    float s0 = 0.f, s1 = 0.f, s2 = 0.f, s3 = 0.f;
#pragma unroll
    for (int k = 0; k < HH; k += 4) {
        float4 h4 = *(const float4*)&hs[k];
        s0 = fmaf(w[k],     h4.x, s0);
        s1 = fmaf(w[k + 1], h4.y, s1);
        s2 = fmaf(w[k + 2], h4.z, s2);
        s3 = fmaf(w[k + 3], h4.w, s3);
    }
    return (s0 + s1) + (s2 + s3);
}

// ---------------------------------------------------------------------------
// Kernel C0: layer-0 GRU scan (cumsum of r folded in). One block per batch.
// ---------------------------------------------------------------------------
__global__ void __launch_bounds__(GG, 1) gru0_kernel(
    const float* __restrict__ Whh0, const float* __restrict__ bih0,
    const float* __restrict__ bhh0)
{
    __shared__ float s_xg[GG];
    __shared__ float s_gh[GG];
    __shared__ float h0s[HH];

    const int b = blockIdx.x;
    const int g = threadIdx.x;

    float w0r[HH];
#pragma unroll
    for (int k = 0; k < HH; k++) w0r[k] = Whh0[g * HH + k];

    float acc   = bih0[g];
    float bhh0r = bhh0[g];

    if (g < HH) h0s[g] = 0.0f;
    __syncthreads();

    const float* rptr = g_R + (size_t)b * LL * GG + g;
    float* hout = g_H0 + (size_t)b * LL * HH;
    float rv_next = rptr[0];

    for (int t = 0; t < LL; t++) {
        float rv = rv_next;
        if (t + 1 < LL) rv_next = rptr[(size_t)(t + 1) * GG];
        acc += rv;

        float gh = bhh0r + dot64(w0r, h0s);
        s_xg[g] = acc;
        s_gh[g] = gh;
        __syncthreads();

        if (g < HH) {
            float r = fast_sigm(s_xg[g] + s_gh[g]);
            float z = fast_sigm(s_xg[HH + g] + s_gh[HH + g]);
            float n = fast_tanh(s_xg[2 * HH + g] + r * s_gh[2 * HH + g]);
            float hn = (1.0f - z) * n + z * h0s[g];
            h0s[g] = hn;
            hout[(size_t)t * HH + g] = hn;
        }
        __syncthreads();
    }
}

// ---------------------------------------------------------------------------
// Kernel C1: layer-1 GRU scan. Wih1 + Whh1 rows in registers; h0 prefetched.
// ---------------------------------------------------------------------------
__global__ void __launch_bounds__(GG, 1) gru1_kernel(
    const float* __restrict__ Wih1, const float* __restrict__ Whh1,
    const float* __restrict__ bih1, const float* __restrict__ bhh1,
    float* __restrict__ out)
{
    __shared__ float s_xg[GG];
    __shared__ float s_gh[GG];
    __shared__ float h0s[HH];
    __shared__ float h1s[HH];

    const int b = blockIdx.x;
    const int g = threadIdx.x;

    float wir[HH], whr[HH];
#pragma unroll
    for (int k = 0; k < HH; k++) wir[k] = Wih1[g * HH + k];
#pragma unroll
    for (int k = 0; k < HH; k++) whr[k] = Whh1[g * HH + k];

    float bih1r = bih1[g];
    float bhh1r = bhh1[g];

    if (g < HH) h1s[g] = 0.0f;
    __syncthreads();

    const float* hin = g_H0 + (size_t)b * LL * HH;

    float hreg = (g < HH) ? hin[g] : 0.0f;   // prefetched h0[t]

    for (int t = 0; t < LL; t++) {
        if (g < HH) h0s[g] = hreg;
        __syncthreads();
        if (g < HH && t + 1 < LL) hreg = hin[(size_t)(t + 1) * HH + g];  // prefetch

        float xg = bih1r + dot64(wir, h0s);
        float gh = bhh1r + dot64(whr, h1s);
        s_xg[g] = xg;
        s_gh[g] = gh;
        __syncthreads();

        if (g < HH) {
            float r = fast_sigm(s_xg[g] + s_gh[g]);
            float z = fast_sigm(s_xg[HH + g] + s_gh[HH + g]);
            float n = fast_tanh(s_xg[2 * HH + g] + r * s_gh[2 * HH + g]);
            float hn = (1.0f - z) * n + z * h1s[g];
            h1s[g] = hn;
            out[((size_t)b * LL + t) * HH + g] = hn;
        }
        __syncthreads();
    }
}

// ---------------------------------------------------------------------------
extern "C" void kernel_launch(void* const* d_in, const int* in_sizes, int n_in,
                              void* d_out, int out_size)
{
    const float* x    = (const float*)d_in[0];
    const float* cw1  = (const float*)d_in[1];
    const float* cb1  = (const float*)d_in[2];
    const float* cw2  = (const float*)d_in[3];
    const float* cb2  = (const float*)d_in[4];
    const float* Wih0 = (const float*)d_in[5];
    const float* Whh0 = (const float*)d_in[6];
    const float* bih0 = (const float*)d_in[7];
    const float* bhh0 = (const float*)d_in[8];
    const float* Wih1 = (const float*)d_in[9];
    const float* Whh1 = (const float*)d_in[10];
    const float* bih1 = (const float*)d_in[11];
    const float* bhh1 = (const float*)d_in[12];
    float* out = (float*)d_out;

    augment_kernel<<<BB, LL>>>(x, cw1, cb1, cw2, cb2);

    dim3 gridB(LL / 64, GG / 64, BB);
    siggemm_kernel<<<gridB, 256>>>(Wih0);

    gru0_kernel<<<BB, GG>>>(Whh0, bih0, bhh0);
    gru1_kernel<<<BB, GG>>>(Wih1, Whh1, bih1, bhh1, out);
}

// round 5
// speedup vs baseline: 1.1889x; 1.0957x over previous
#include <cuda_runtime.h>
#include <math.h>

#define BB 64
#define LL 256
#define DIN 55
#define AH 32
#define AC 8
#define CC 64
#define GG 192
#define HH 64
#define SIGW 4160   // CC + CC*CC

// Scratch (device globals — no runtime allocation allowed)
__device__ float g_P[(size_t)BB * CC * LL];        // p in [b][c][t] layout, 4 MB
__device__ float g_R[(size_t)BB * LL * GG];        // per-step projection increments, 12.6 MB

// ---------------------------------------------------------------------------
// Kernel A: Augment. p = concat(x, time, relu(x W1^T + b1) W2^T + b2)
// ---------------------------------------------------------------------------
__global__ void __launch_bounds__(LL) augment_kernel(
    const float* __restrict__ x,
    const float* __restrict__ w1, const float* __restrict__ b1,
    const float* __restrict__ w2, const float* __restrict__ b2)
{
    __shared__ float w1s[AH * DIN];
    __shared__ float w2s[AC * AH];
    __shared__ float b1s[AH];
    __shared__ float b2s[AC];

    int b = blockIdx.x;
    int t = threadIdx.x;

    for (int i = threadIdx.x; i < AH * DIN; i += blockDim.x) w1s[i] = w1[i];
    for (int i = threadIdx.x; i < AC * AH; i += blockDim.x)  w2s[i] = w2[i];
    if (threadIdx.x < AH) b1s[threadIdx.x] = b1[threadIdx.x];
    if (threadIdx.x < AC) b2s[threadIdx.x] = b2[threadIdx.x];
    __syncthreads();

    float xv[DIN];
    const float* xp = x + ((size_t)b * LL + t) * DIN;
#pragma unroll
    for (int c = 0; c < DIN; c++) xv[c] = xp[c];

    float hb[AH];
#pragma unroll
    for (int h = 0; h < AH; h++) {
        float acc = b1s[h];
#pragma unroll
        for (int c = 0; c < DIN; c++) acc += w1s[h * DIN + c] * xv[c];
        hb[h] = fmaxf(acc, 0.0f);
    }

    float* Pp = g_P + (size_t)b * CC * LL + t;   // [b][c][t]: stride LL per channel
#pragma unroll
    for (int c = 0; c < DIN; c++) Pp[(size_t)c * LL] = xv[c];
    Pp[(size_t)DIN * LL] = (float)t / (float)(LL - 1);
#pragma unroll
    for (int a = 0; a < AC; a++) {
        float acc = b2s[a];
#pragma unroll
        for (int h = 0; h < AH; h++) acc += w2s[a * AH + h] * hb[h];
        Pp[(size_t)(DIN + 1 + a) * LL] = acc;
    }
}

// ---------------------------------------------------------------------------
// f32x2 packed helpers (Blackwell)
// ---------------------------------------------------------------------------
#define FMA2(d, a, b, c) \
    asm("fma.rn.f32x2 %0, %1, %2, %3;" : "=l"(d) : "l"(a), "l"(b), "l"(c))
#define PACK2(out, lo, hi) \
    asm("mov.b64 %0, {%1, %2};" : "=l"(out) : "r"(lo), "r"(hi))

// ---------------------------------------------------------------------------
// Kernel B (v2): r[b,t,g] = W[g,0:64].d + sum_ij W[g,64+64i+j] a_i d_j
// 64 threads/block, 8 gates x 8 positions per thread, f32x2 accumulators.
// Block tile 64 gates x 64 positions. 4 blocks/SM (48 KB smem each).
// ---------------------------------------------------------------------------
__global__ void __launch_bounds__(64, 4) siggemm_kernel(const float* __restrict__ Wih0)
{
    __shared__ float a_s[CC][64];     // [i][p]
    __shared__ float d_s[CC][64];     // [j][p]
    __shared__ float Wt_s[64][64];    // [j][g]  (transposed W tile)

    const int t0    = blockIdx.x * 64;
    const int gbase = blockIdx.y * 64;
    const int b     = blockIdx.z;
    const int tid   = threadIdx.x;
    const int gi    = tid >> 3;   // 0..7  -> gates   gbase + gi*8 .. +7
    const int pi    = tid & 7;    // 0..7  -> positions t0 + pi*8 .. +7

    // Stage a/d tiles: thread tid owns column tt = tid for every channel c.
    {
        const float* Pb = g_P + (size_t)b * CC * LL;
        int t = t0 + tid;
#pragma unroll 4
        for (int c = 0; c < CC; c++) {
            const float* Pc = Pb + (size_t)c * LL;
            float cur  = Pc[t];
            float prev = (t == 0) ? 0.0f : Pc[t - 1];
            d_s[c][tid] = cur - prev;
            a_s[c][tid] = 0.5f * (cur + prev);
        }
    }

    // Gate-paired accumulators: acc[q][p] = f32x2 over gates (gi*8+2q, gi*8+2q+1)
    unsigned long long acc[4][8];
#pragma unroll
    for (int q = 0; q < 4; q++)
#pragma unroll
        for (int p = 0; p < 8; p++) acc[q][p] = 0ull;

    const float* wrow = Wih0 + (size_t)(gbase + tid) * SIGW;   // this thread's staging gate row

    for (int i = -1; i < CC; i++) {
        __syncthreads();
        // Stage W^T tile: thread tid = gate column g; rows j = K offsets.
        const int koff = (i < 0) ? 0 : (CC + i * CC);
        const float* wr = wrow + koff;
#pragma unroll
        for (int j0 = 0; j0 < 64; j0 += 4) {
            float4 w4 = *(const float4*)(wr + j0);
            Wt_s[j0 + 0][tid] = w4.x;
            Wt_s[j0 + 1][tid] = w4.y;
            Wt_s[j0 + 2][tid] = w4.z;
            Wt_s[j0 + 3][tid] = w4.w;
        }
        __syncthreads();

        // a values for this K-step (1.0 for the level-1 pass)
        float a_r[8];
        if (i < 0) {
#pragma unroll
            for (int p = 0; p < 8; p++) a_r[p] = 1.0f;
        } else {
            float4 a0 = *(const float4*)&a_s[i][pi * 8];
            float4 a1 = *(const float4*)&a_s[i][pi * 8 + 4];
            a_r[0] = a0.x; a_r[1] = a0.y; a_r[2] = a0.z; a_r[3] = a0.w;
            a_r[4] = a1.x; a_r[5] = a1.y; a_r[6] = a1.z; a_r[7] = a1.w;
        }

#pragma unroll 8
        for (int j = 0; j < 64; j++) {
            // 4 gate-pairs of W (native 64-bit pairs from LDS.128)
            ulonglong2 w01 = *(const ulonglong2*)&Wt_s[j][gi * 8];
            ulonglong2 w23 = *(const ulonglong2*)&Wt_s[j][gi * 8 + 4];
            // 8 positions of d
            float4 dv0 = *(const float4*)&d_s[j][pi * 8];
            float4 dv1 = *(const float4*)&d_s[j][pi * 8 + 4];
            float bsc[8];
            bsc[0] = a_r[0] * dv0.x; bsc[1] = a_r[1] * dv0.y;
            bsc[2] = a_r[2] * dv0.z; bsc[3] = a_r[3] * dv0.w;
            bsc[4] = a_r[4] * dv1.x; bsc[5] = a_r[5] * dv1.y;
            bsc[6] = a_r[6] * dv1.z; bsc[7] = a_r[7] * dv1.w;
#pragma unroll
            for (int p = 0; p < 8; p++) {
                unsigned long long bb;
                unsigned int bu = __float_as_uint(bsc[p]);
                PACK2(bb, bu, bu);
                FMA2(acc[0][p], w01.x, bb, acc[0][p]);
                FMA2(acc[1][p], w01.y, bb, acc[1][p]);
                FMA2(acc[2][p], w23.x, bb, acc[2][p]);
                FMA2(acc[3][p], w23.y, bb, acc[3][p]);
            }
        }
    }

    // Epilogue: unpack gate pairs, write r[b][t][g]
#pragma unroll
    for (int p = 0; p < 8; p++) {
        int t = t0 + pi * 8 + p;
        float* rp = g_R + ((size_t)b * LL + t) * GG + gbase + gi * 8;
        float2 a0 = *(float2*)&acc[0][p];
        float2 a1 = *(float2*)&acc[1][p];
        float2 a2 = *(float2*)&acc[2][p];
        float2 a3 = *(float2*)&acc[3][p];
        *(float4*)(rp)     = make_float4(a0.x, a0.y, a1.x, a1.y);
        *(float4*)(rp + 4) = make_float4(a2.x, a2.y, a3.x, a3.y);
    }
}

// ---------------------------------------------------------------------------
// Fast activations
// ---------------------------------------------------------------------------
__device__ __forceinline__ float fast_sigm(float v) {
    return __fdividef(1.0f, 1.0f + __expf(-v));
}
__device__ __forceinline__ float fast_tanh(float v) {
    v = fminf(fmaxf(v, -10.0f), 10.0f);
    float e = __expf(2.0f * v);
    return __fdividef(e - 1.0f, e + 1.0f);
}

__device__ __forceinline__ float dot64(const float* __restrict__ w,
                                       const float* __restrict__ hs) {
    float s0 = 0.f, s1 = 0.f, s2 = 0.f, s3 = 0.f;
#pragma unroll
    for (int k = 0; k < HH; k += 4) {
        float4 h4 = *(const float4*)&hs[k];
        s0 = fmaf(w[k],     h4.x, s0);
        s1 = fmaf(w[k + 1], h4.y, s1);
        s2 = fmaf(w[k + 2], h4.z, s2);
        s3 = fmaf(w[k + 3], h4.w, s3);
    }
    return (s0 + s1) + (s2 + s3);
}

// ---------------------------------------------------------------------------
// Kernel C: fused 2-layer GRU, software-pipelined: layer 1 runs one timestep
// behind layer 0 so both layers' matvecs execute concurrently.
// 576 threads = 3 roles x 192 gates. One block per batch element.
//   role 0: gh0 = Whh0 . h0[s-1]   (+ cumsum xg0)
//   role 1: xg1 = Wih1 . h0[s-1]
//   role 2: gh1 = Whh1 . h1[s-2]
// ---------------------------------------------------------------------------
__global__ void __launch_bounds__(3 * GG, 1) gru_fused_kernel(
    const float* __restrict__ Whh0, const float* __restrict__ bih0, const float* __restrict__ bhh0,
    const float* __restrict__ Wih1, const float* __restrict__ Whh1,
    const float* __restrict__ bih1, const float* __restrict__ bhh1,
    float* __restrict__ out)
{
    __shared__ float h0buf[2][HH];
    __shared__ float h1s[HH];
    __shared__ float s_xg0[GG], s_gh0[GG], s_xg1[GG], s_gh1[GG];

    const int b    = blockIdx.x;
    const int tid  = threadIdx.x;
    const int role = tid / GG;   // 0,1,2
    const int g    = tid - role * GG;

    const float* wsrc = (role == 0) ? Whh0 : (role == 1) ? Wih1 : Whh1;
    float wreg[HH];
#pragma unroll
    for (int k = 0; k < HH; k++) wreg[k] = wsrc[g * HH + k];

    const float bias = (role == 0) ? bhh0[g] : (role == 1) ? bih1[g] : bhh1[g];

    // role-0 cumsum state + r prefetch
    float acc = 0.0f, rv_next = 0.0f;
    const float* rptr = g_R + (size_t)b * LL * GG + g;
    if (role == 0) { acc = bih0[g]; rv_next = rptr[0]; }

    if (tid < HH) { h0buf[0][tid] = 0.0f; h0buf[1][tid] = 0.0f; h1s[tid] = 0.0f; }
    __syncthreads();

    for (int s = 0; s <= LL; s++) {
        const float* hprev0 = h0buf[(s + 1) & 1];   // h0[s-1]

        if (role == 0) {
            if (s < LL) {
                float rv = rv_next;
                if (s + 1 < LL) rv_next = rptr[(size_t)(s + 1) * GG];
                acc += rv;
                s_xg0[g] = acc;
                s_gh0[g] = bias + dot64(wreg, hprev0);
            }
        } else if (role == 1) {
            if (s >= 1) s_xg1[g] = bias + dot64(wreg, hprev0);
        } else {
            if (s >= 1) s_gh1[g] = bias + dot64(wreg, h1s);
        }
        __syncthreads();

        if (tid < HH) {
            if (s < LL) {
                float r = fast_sigm(s_xg0[tid] + s_gh0[tid]);
                float z = fast_sigm(s_xg0[HH + tid] + s_gh0[HH + tid]);
                float n = fast_tanh(s_xg0[2 * HH + tid] + r * s_gh0[2 * HH + tid]);
                h0buf[s & 1][tid] = (1.0f - z) * n + z * hprev0[tid];
            }
        } else if (tid >= GG && tid < GG + HH) {
            if (s >= 1) {
                int q = tid - GG;
                float r = fast_sigm(s_xg1[q] + s_gh1[q]);
                float z = fast_sigm(s_xg1[HH + q] + s_gh1[HH + q]);
                float n = fast_tanh(s_xg1[2 * HH + q] + r * s_gh1[2 * HH + q]);
                float hn = (1.0f - z) * n + z * h1s[q];
                h1s[q] = hn;
                out[((size_t)b * LL + (s - 1)) * HH + q] = hn;
            }
        }
        __syncthreads();
    }
}

// ---------------------------------------------------------------------------
extern "C" void kernel_launch(void* const* d_in, const int* in_sizes, int n_in,
                              void* d_out, int out_size)
{
    const float* x    = (const float*)d_in[0];
    const float* cw1  = (const float*)d_in[1];
    const float* cb1  = (const float*)d_in[2];
    const float* cw2  = (const float*)d_in[3];
    const float* cb2  = (const float*)d_in[4];
    const float* Wih0 = (const float*)d_in[5];
    const float* Whh0 = (const float*)d_in[6];
    const float* bih0 = (const float*)d_in[7];
    const float* bhh0 = (const float*)d_in[8];
    const float* Wih1 = (const float*)d_in[9];
    const float* Whh1 = (const float*)d_in[10];
    const float* bih1 = (const float*)d_in[11];
    const float* bhh1 = (const float*)d_in[12];
    float* out = (float*)d_out;

    augment_kernel<<<BB, LL>>>(x, cw1, cb1, cw2, cb2);

    dim3 gridB(LL / 64, GG / 64, BB);
    siggemm_kernel<<<gridB, 64>>>(Wih0);

    gru_fused_kernel<<<BB, 3 * GG>>>(Whh0, bih0, bhh0,
                                     Wih1, Whh1, bih1, bhh1, out);
}

// round 7
// speedup vs baseline: 1.5046x; 1.2655x over previous
#include <cuda_runtime.h>
#include <math.h>
#include <stdint.h>

#define BB 64
#define LL 256
#define DIN 55
#define AH 32
#define AC 8
#define CC 64
#define GG 192
#define HH 64
#define SIGW 4160   // CC + CC*CC

// Scratch (device globals — no runtime allocation allowed)
__device__ float g_P[(size_t)BB * CC * LL];        // p in [b][c][t] layout, 4 MB
__device__ float g_R[(size_t)BB * LL * GG];        // per-step projection increments, 12.6 MB

// ---------------------------------------------------------------------------
// Kernel A: Augment. p = concat(x, time, relu(x W1^T + b1) W2^T + b2)
// ---------------------------------------------------------------------------
__global__ void __launch_bounds__(LL) augment_kernel(
    const float* __restrict__ x,
    const float* __restrict__ w1, const float* __restrict__ b1,
    const float* __restrict__ w2, const float* __restrict__ b2)
{
    __shared__ float w1s[AH * DIN];
    __shared__ float w2s[AC * AH];
    __shared__ float b1s[AH];
    __shared__ float b2s[AC];

    int b = blockIdx.x;
    int t = threadIdx.x;

    for (int i = threadIdx.x; i < AH * DIN; i += blockDim.x) w1s[i] = w1[i];
    for (int i = threadIdx.x; i < AC * AH; i += blockDim.x)  w2s[i] = w2[i];
    if (threadIdx.x < AH) b1s[threadIdx.x] = b1[threadIdx.x];
    if (threadIdx.x < AC) b2s[threadIdx.x] = b2[threadIdx.x];
    __syncthreads();

    float xv[DIN];
    const float* xp = x + ((size_t)b * LL + t) * DIN;
#pragma unroll
    for (int c = 0; c < DIN; c++) xv[c] = xp[c];

    float hb[AH];
#pragma unroll
    for (int h = 0; h < AH; h++) {
        float acc = b1s[h];
#pragma unroll
        for (int c = 0; c < DIN; c++) acc += w1s[h * DIN + c] * xv[c];
        hb[h] = fmaxf(acc, 0.0f);
    }

    float* Pp = g_P + (size_t)b * CC * LL + t;   // [b][c][t]: stride LL per channel
#pragma unroll
    for (int c = 0; c < DIN; c++) Pp[(size_t)c * LL] = xv[c];
    Pp[(size_t)DIN * LL] = (float)t / (float)(LL - 1);
#pragma unroll
    for (int a = 0; a < AC; a++) {
        float acc = b2s[a];
#pragma unroll
        for (int h = 0; h < AH; h++) acc += w2s[a * AH + h] * hb[h];
        Pp[(size_t)(DIN + 1 + a) * LL] = acc;
    }
}

// ---------------------------------------------------------------------------
// tf32 helpers
// ---------------------------------------------------------------------------
__device__ __forceinline__ uint32_t f2tf(float x) {
    uint32_t r;
    asm("cvt.rna.tf32.f32 %0, %1;" : "=r"(r) : "f"(x));
    return r;
}
// hi/lo split: x ~= as_float(hi) + as_float(lo), each tf32-representable
__device__ __forceinline__ void tf_split(float x, uint32_t& hi, uint32_t& lo) {
    hi = f2tf(x);
    lo = f2tf(x - __uint_as_float(hi));
}

#define MMA_TF32(c0, c1, c2, c3, a0, a1, a2, a3, b0, b1)                       \
    asm volatile(                                                              \
        "mma.sync.aligned.m16n8k8.row.col.f32.tf32.tf32.f32 "                  \
        "{%0,%1,%2,%3}, {%4,%5,%6,%7}, {%8,%9}, {%0,%1,%2,%3};"                \
        : "+f"(c0), "+f"(c1), "+f"(c2), "+f"(c3)                               \
        : "r"(a0), "r"(a1), "r"(a2), "r"(a3), "r"(b0), "r"(b1))

// ---------------------------------------------------------------------------
// Kernel B (3xTF32 tensor-core): R[p, g] = sum_k A[p,k] W[g,k]
//   A chunk i=-1 : d[p][j];  chunk i>=0 : a_i[p] * d[p][j]
// Block tile: 64 positions x 96 gates. Grid: (256 position tiles, 2 gate tiles).
// 256 thr = 8 warps (2 M-warps x 4 N-warps, 3 n-frags each).
// Dyn smem 87040 B: d[64][68] | a[64][68] | Whi[96][68] | Wlo[96][68].
// ---------------------------------------------------------------------------
#define PADW 68
#define GT 96
#define SMEM_TC_BYTES ((64 * PADW + 64 * PADW + 2 * GT * PADW) * 4)

__global__ void __launch_bounds__(256, 2) siggemm_tc_kernel(const float* __restrict__ Wih0)
{
    extern __shared__ float smem[];
    float* d_s = smem;                                   // [p][j]
    float* a_s = smem + 64 * PADW;                       // [i][p]
    uint32_t* Whi_s = (uint32_t*)(smem + 2 * 64 * PADW); // [g][j]
    uint32_t* Wlo_s = Whi_s + GT * PADW;                 // [g][j]

    const int ptile = blockIdx.x;         // 0..255
    const int gbase = blockIdx.y * GT;    // 0 or 96
    const int b  = ptile >> 2;
    const int t0 = (ptile & 3) * 64;
    const int tid  = threadIdx.x;
    const int warp = tid >> 5;
    const int lane = tid & 31;
    const int warpM = warp & 1;           // rows 32*warpM..+31
    const int warpN = warp >> 1;          // gates gbase + 24*warpN..+23
    const int lq = lane >> 2;
    const int lr = lane & 3;

    // ---- stage d/a tiles
    {
        const float* Pb = g_P + (size_t)b * CC * LL;
        for (int idx = tid; idx < 64 * 64; idx += 256) {
            int j = idx >> 6;
            int p = idx & 63;
            int t = t0 + p;
            const float* Pc = Pb + (size_t)j * LL;
            float cur  = Pc[t];
            float prev = (t == 0) ? 0.0f : Pc[t - 1];
            d_s[p * PADW + j] = cur - prev;
            a_s[j * PADW + p] = 0.5f * (cur + prev);
        }
    }

    float acc[2][3][4];
#pragma unroll
    for (int mf = 0; mf < 2; mf++)
#pragma unroll
        for (int nf = 0; nf < 3; nf++)
#pragma unroll
            for (int q = 0; q < 4; q++) acc[mf][nf][q] = 0.0f;

    for (int i = -1; i < CC; i++) {
        __syncthreads();
        // ---- stage W chunk (96 gates x 64 ch) as tf32 hi/lo
        const int koff = (i < 0) ? 0 : (CC + i * CC);
        for (int idx = tid; idx < GT * 16; idx += 256) {
            int g  = idx >> 4;
            int j4 = (idx & 15) * 4;
            float4 w4 = *(const float4*)(Wih0 + (size_t)(gbase + g) * SIGW + koff + j4);
            uint32_t* hp = Whi_s + g * PADW + j4;
            uint32_t* lp = Wlo_s + g * PADW + j4;
            tf_split(w4.x, hp[0], lp[0]);
            tf_split(w4.y, hp[1], lp[1]);
            tf_split(w4.z, hp[2], lp[2]);
            tf_split(w4.w, hp[3], lp[3]);
        }
        __syncthreads();

        float av[2][2];
#pragma unroll
        for (int mf = 0; mf < 2; mf++) {
            int r0 = warpM * 32 + mf * 16 + lq;
            if (i < 0) { av[mf][0] = 1.0f; av[mf][1] = 1.0f; }
            else {
                av[mf][0] = a_s[i * PADW + r0];
                av[mf][1] = a_s[i * PADW + r0 + 8];
            }
        }

#pragma unroll
        for (int s = 0; s < 8; s++) {
            const int kb = s * 8;
            // A fragments (generated): x = a_i[r]*d[r][c], hi/lo split
            uint32_t ahi[2][4], alo[2][4];
#pragma unroll
            for (int mf = 0; mf < 2; mf++) {
                int rbase = warpM * 32 + mf * 16 + lq;
                const float* dr0 = d_s + rbase * PADW + kb + lr;
                const float* dr1 = d_s + (rbase + 8) * PADW + kb + lr;
                tf_split(av[mf][0] * dr0[0], ahi[mf][0], alo[mf][0]);
                tf_split(av[mf][1] * dr1[0], ahi[mf][1], alo[mf][1]);
                tf_split(av[mf][0] * dr0[4], ahi[mf][2], alo[mf][2]);
                tf_split(av[mf][1] * dr1[4], ahi[mf][3], alo[mf][3]);
            }
#pragma unroll
            for (int nf = 0; nf < 3; nf++) {
                int n0 = warpN * 24 + nf * 8 + lq;
                uint32_t b0h = Whi_s[n0 * PADW + kb + lr];
                uint32_t b1h = Whi_s[n0 * PADW + kb + 4 + lr];
                uint32_t b0l = Wlo_s[n0 * PADW + kb + lr];
                uint32_t b1l = Wlo_s[n0 * PADW + kb + 4 + lr];
#pragma unroll
                for (int mf = 0; mf < 2; mf++) {
                    MMA_TF32(acc[mf][nf][0], acc[mf][nf][1], acc[mf][nf][2], acc[mf][nf][3],
                             ahi[mf][0], ahi[mf][1], ahi[mf][2], ahi[mf][3], b0h, b1h);
                    MMA_TF32(acc[mf][nf][0], acc[mf][nf][1], acc[mf][nf][2], acc[mf][nf][3],
                             alo[mf][0], alo[mf][1], alo[mf][2], alo[mf][3], b0h, b1h);
                    MMA_TF32(acc[mf][nf][0], acc[mf][nf][1], acc[mf][nf][2], acc[mf][nf][3],
                             ahi[mf][0], ahi[mf][1], ahi[mf][2], ahi[mf][3], b0l, b1l);
                }
            }
        }
    }

    // ---- epilogue
#pragma unroll
    for (int mf = 0; mf < 2; mf++) {
        int trow = t0 + warpM * 32 + mf * 16 + lq;
#pragma unroll
        for (int nf = 0; nf < 3; nf++) {
            int g = gbase + warpN * 24 + nf * 8 + 2 * lr;
            float* rp0 = g_R + ((size_t)b * LL + trow) * GG + g;
            float* rp1 = g_R + ((size_t)b * LL + trow + 8) * GG + g;
            *(float2*)rp0 = make_float2(acc[mf][nf][0], acc[mf][nf][1]);
            *(float2*)rp1 = make_float2(acc[mf][nf][2], acc[mf][nf][3]);
        }
    }
}

// ---------------------------------------------------------------------------
// Fast activations
// ---------------------------------------------------------------------------
__device__ __forceinline__ float fast_sigm(float v) {
    return __fdividef(1.0f, 1.0f + __expf(-v));
}
__device__ __forceinline__ float fast_tanh(float v) {
    v = fminf(fmaxf(v, -10.0f), 10.0f);
    float e = __expf(2.0f * v);
    return __fdividef(e - 1.0f, e + 1.0f);
}

__device__ __forceinline__ float dot64(const float* __restrict__ w,
                                       const float* __restrict__ hs) {
    float s0 = 0.f, s1 = 0.f, s2 = 0.f, s3 = 0.f;
#pragma unroll
    for (int k = 0; k < HH; k += 4) {
        float4 h4 = *(const float4*)&hs[k];
        s0 = fmaf(w[k],     h4.x, s0);
        s1 = fmaf(w[k + 1], h4.y, s1);
        s2 = fmaf(w[k + 2], h4.z, s2);
        s3 = fmaf(w[k + 3], h4.w, s3);
    }
    return (s0 + s1) + (s2 + s3);
}

// ---------------------------------------------------------------------------
// Kernel C: fused 2-layer GRU, software-pipelined (layer 1 one step behind).
// 576 threads = 3 roles x 192 gates. One block per batch element.
// ---------------------------------------------------------------------------
__global__ void __launch_bounds__(3 * GG, 1) gru_fused_kernel(
    const float* __restrict__ Whh0, const float* __restrict__ bih0, const float* __restrict__ bhh0,
    const float* __restrict__ Wih1, const float* __restrict__ Whh1,
    const float* __restrict__ bih1, const float* __restrict__ bhh1,
    float* __restrict__ out)
{
    __shared__ float h0buf[2][HH];
    __shared__ float h1s[HH];
    __shared__ float s_xg0[GG], s_gh0[GG], s_xg1[GG], s_gh1[GG];

    const int b    = blockIdx.x;
    const int tid  = threadIdx.x;
    const int role = tid / GG;   // 0,1,2
    const int g    = tid - role * GG;

    const float* wsrc = (role == 0) ? Whh0 : (role == 1) ? Wih1 : Whh1;
    float wreg[HH];
#pragma unroll
    for (int k = 0; k < HH; k++) wreg[k] = wsrc[g * HH + k];

    const float bias = (role == 0) ? bhh0[g] : (role == 1) ? bih1[g] : bhh1[g];

    float acc = 0.0f, rv_next = 0.0f;
    const float* rptr = g_R + (size_t)b * LL * GG + g;
    if (role == 0) { acc = bih0[g]; rv_next = rptr[0]; }

    if (tid < HH) { h0buf[0][tid] = 0.0f; h0buf[1][tid] = 0.0f; h1s[tid] = 0.0f; }
    __syncthreads();

    for (int s = 0; s <= LL; s++) {
        const float* hprev0 = h0buf[(s + 1) & 1];   // h0[s-1]

        if (role == 0) {
            if (s < LL) {
                float rv = rv_next;
                if (s + 1 < LL) rv_next = rptr[(size_t)(s + 1) * GG];
                acc += rv;
                s_xg0[g] = acc;
                s_gh0[g] = bias + dot64(wreg, hprev0);
            }
        } else if (role == 1) {
            if (s >= 1) s_xg1[g] = bias + dot64(wreg, hprev0);
        } else {
            if (s >= 1) s_gh1[g] = bias + dot64(wreg, h1s);
        }
        __syncthreads();

        if (tid < HH) {
            if (s < LL) {
                float r = fast_sigm(s_xg0[tid] + s_gh0[tid]);
                float z = fast_sigm(s_xg0[HH + tid] + s_gh0[HH + tid]);
                float n = fast_tanh(s_xg0[2 * HH + tid] + r * s_gh0[2 * HH + tid]);
                h0buf[s & 1][tid] = (1.0f - z) * n + z * hprev0[tid];
            }
        } else if (tid >= GG && tid < GG + HH) {
            if (s >= 1) {
                int q = tid - GG;
                float r = fast_sigm(s_xg1[q] + s_gh1[q]);
                float z = fast_sigm(s_xg1[HH + q] + s_gh1[HH + q]);
                float n = fast_tanh(s_xg1[2 * HH + q] + r * s_gh1[2 * HH + q]);
                float hn = (1.0f - z) * n + z * h1s[q];
                h1s[q] = hn;
                out[((size_t)b * LL + (s - 1)) * HH + q] = hn;
            }
        }
        __syncthreads();
    }
}

// ---------------------------------------------------------------------------
extern "C" void kernel_launch(void* const* d_in, const int* in_sizes, int n_in,
                              void* d_out, int out_size)
{
    const float* x    = (const float*)d_in[0];
    const float* cw1  = (const float*)d_in[1];
    const float* cb1  = (const float*)d_in[2];
    const float* cw2  = (const float*)d_in[3];
    const float* cb2  = (const float*)d_in[4];
    const float* Wih0 = (const float*)d_in[5];
    const float* Whh0 = (const float*)d_in[6];
    const float* bih0 = (const float*)d_in[7];
    const float* bhh0 = (const float*)d_in[8];
    const float* Wih1 = (const float*)d_in[9];
    const float* Whh1 = (const float*)d_in[10];
    const float* bih1 = (const float*)d_in[11];
    const float* bhh1 = (const float*)d_in[12];
    float* out = (float*)d_out;

    // opt-in to >48KB dynamic smem (host attribute set, not an allocation)
    cudaFuncSetAttribute(siggemm_tc_kernel,
                         cudaFuncAttributeMaxDynamicSharedMemorySize, SMEM_TC_BYTES);

    augment_kernel<<<BB, LL>>>(x, cw1, cb1, cw2, cb2);

    dim3 gridB(256, 2);
    siggemm_tc_kernel<<<gridB, 256, SMEM_TC_BYTES>>>(Wih0);

    gru_fused_kernel<<<BB, 3 * GG>>>(Whh0, bih0, bhh0,
                                     Wih1, Whh1, bih1, bhh1, out);
}

// round 8
// speedup vs baseline: 2.4902x; 1.6551x over previous
#include <cuda_runtime.h>
#include <cuda_bf16.h>
#include <math.h>
#include <stdint.h>

#define BB 64
#define LL 256
#define DIN 55
#define AH 32
#define AC 8
#define CC 64
#define GG 192
#define HH 64
#define SIGW 4160   // CC + CC*CC

// Scratch (device globals — no runtime allocation allowed)
__device__ float g_P[(size_t)BB * CC * LL];        // p in [b][c][t] layout, 4 MB
__device__ float g_R[(size_t)BB * LL * GG];        // per-step projection increments, 12.6 MB

// ---------------------------------------------------------------------------
// Kernel A: Augment. p = concat(x, time, relu(x W1^T + b1) W2^T + b2)
// ---------------------------------------------------------------------------
__global__ void __launch_bounds__(LL) augment_kernel(
    const float* __restrict__ x,
    const float* __restrict__ w1, const float* __restrict__ b1,
    const float* __restrict__ w2, const float* __restrict__ b2)
{
    __shared__ float w1s[AH * DIN];
    __shared__ float w2s[AC * AH];
    __shared__ float b1s[AH];
    __shared__ float b2s[AC];

    int b = blockIdx.x;
    int t = threadIdx.x;

    for (int i = threadIdx.x; i < AH * DIN; i += blockDim.x) w1s[i] = w1[i];
    for (int i = threadIdx.x; i < AC * AH; i += blockDim.x)  w2s[i] = w2[i];
    if (threadIdx.x < AH) b1s[threadIdx.x] = b1[threadIdx.x];
    if (threadIdx.x < AC) b2s[threadIdx.x] = b2[threadIdx.x];
    __syncthreads();

    float xv[DIN];
    const float* xp = x + ((size_t)b * LL + t) * DIN;
#pragma unroll
    for (int c = 0; c < DIN; c++) xv[c] = xp[c];

    float hb[AH];
#pragma unroll
    for (int h = 0; h < AH; h++) {
        float acc = b1s[h];
#pragma unroll
        for (int c = 0; c < DIN; c++) acc += w1s[h * DIN + c] * xv[c];
        hb[h] = fmaxf(acc, 0.0f);
    }

    float* Pp = g_P + (size_t)b * CC * LL + t;   // [b][c][t]: stride LL per channel
#pragma unroll
    for (int c = 0; c < DIN; c++) Pp[(size_t)c * LL] = xv[c];
    Pp[(size_t)DIN * LL] = (float)t / (float)(LL - 1);
#pragma unroll
    for (int a = 0; a < AC; a++) {
        float acc = b2s[a];
#pragma unroll
        for (int h = 0; h < AH; h++) acc += w2s[a * AH + h] * hb[h];
        Pp[(size_t)(DIN + 1 + a) * LL] = acc;
    }
}

// ---------------------------------------------------------------------------
// bf16 helpers
// ---------------------------------------------------------------------------
__device__ __forceinline__ float bf_hi(float x) {
    return __bfloat162float(__float2bfloat16_rn(x));
}
__device__ __forceinline__ uint32_t bfpack(float x, float y) {
    __nv_bfloat162 t = __floats2bfloat162_rn(x, y);   // .x = x (low 16 bits)
    return *reinterpret_cast<uint32_t*>(&t);
}

#define MMA_BF16(c0, c1, c2, c3, a0, a1, a2, a3, b0, b1)                       \
    asm volatile(                                                              \
        "mma.sync.aligned.m16n8k16.row.col.f32.bf16.bf16.f32 "                 \
        "{%0,%1,%2,%3}, {%4,%5,%6,%7}, {%8,%9}, {%0,%1,%2,%3};"                \
        : "+f"(c0), "+f"(c1), "+f"(c2), "+f"(c3)                               \
        : "r"(a0), "r"(a1), "r"(a2), "r"(a3), "r"(b0), "r"(b1))

// ---------------------------------------------------------------------------
// Kernel B (bf16 split tensor-core):
//   R[p,g] = sum_c  scale_c[p] * (D  W_c^T)[p,g]
//   chunk c=0:  W cols [0,64),  scale = 1              (level-1 term)
//   chunk c>=1: W cols [64+ (c-1)*64, ...), scale = a_{c-1}[p]
// D (64 pos x 64 ch) split hi/lo bf16 ONCE; A-fragments live in registers for
// the whole kernel. W chunk prefetched to registers one chunk ahead.
// 3-product bf16 split (hh + lh + hl) ~ fp32 accuracy (per-elem ~2^-16).
// Block: 256 thr = 8 warps (2 M x 4 N). Tile: 64 pos x 96 gates.
// Grid: (256 position tiles, 2 gate tiles).
// ---------------------------------------------------------------------------
#define PADH 36   // half2 row stride: (36*2+... ) -> banks 4*lq+lr distinct mod 32
#define GT 96
// smem: a_s fp32 [64][68] | Dh2/Dl2 half2 [64][36] | Wh2/Wl2 half2 [96][36]
#define SM_A_OFF   0
#define SM_DH_OFF  (64 * 68)                 // in uint32 units after a_s
#define SM_DL_OFF  (SM_DH_OFF + 64 * PADH)
#define SM_WH_OFF  (SM_DL_OFF + 64 * PADH)
#define SM_WL_OFF  (SM_WH_OFF + GT * PADH)
#define SMEM_TC_WORDS (SM_WL_OFF + GT * PADH)
#define SMEM_TC_BYTES (SMEM_TC_WORDS * 4)

__global__ void __launch_bounds__(256) siggemm_bf16_kernel(const float* __restrict__ Wih0)
{
    extern __shared__ uint32_t smw[];
    float*    a_s  = (float*)smw;            // [i][p] stride 68
    uint32_t* Dh2  = smw + SM_DH_OFF;        // [p][PADH]
    uint32_t* Dl2  = smw + SM_DL_OFF;
    uint32_t* Wh2  = smw + SM_WH_OFF;        // [g][PADH]
    uint32_t* Wl2  = smw + SM_WL_OFF;

    const int ptile = blockIdx.x;            // 0..255
    const int gbase = blockIdx.y * GT;       // 0 or 96
    const int b  = ptile >> 2;
    const int t0 = (ptile & 3) * 64;
    const int tid  = threadIdx.x;
    const int warp = tid >> 5;
    const int lane = tid & 31;
    const int warpM = warp & 1;              // rows 32*warpM..+31
    const int warpN = warp >> 1;             // gates 24*warpN..+23 (within tile)
    const int lq = lane >> 2;
    const int lr = lane & 3;

    // ---- stage a (fp32) and D (bf16 hi/lo half2 pairs)
    {
        const float* Pb = g_P + (size_t)b * CC * LL;
        for (int idx = tid; idx < 64 * 32; idx += 256) {
            int j2 = idx >> 6;               // channel pair 0..31
            int p  = idx & 63;               // local position
            int t  = t0 + p;
            const float* Pc0 = Pb + (size_t)(2 * j2) * LL;
            const float* Pc1 = Pc0 + LL;
            float c0 = Pc0[t], p0 = (t == 0) ? 0.0f : Pc0[t - 1];
            float c1 = Pc1[t], p1 = (t == 0) ? 0.0f : Pc1[t - 1];
            float d0 = c0 - p0, d1 = c1 - p1;
            a_s[(2 * j2) * 68 + p]     = 0.5f * (c0 + p0);
            a_s[(2 * j2 + 1) * 68 + p] = 0.5f * (c1 + p1);
            float h0 = bf_hi(d0), h1 = bf_hi(d1);
            Dh2[p * PADH + j2] = bfpack(h0, h1);
            Dl2[p * PADH + j2] = bfpack(d0 - h0, d1 - h1);
        }
    }
    __syncthreads();

    // ---- load chunk-invariant A fragments (D hi/lo) into registers
    uint32_t Ah[2][4][4], Al[2][4][4];
#pragma unroll
    for (int mf = 0; mf < 2; mf++) {
        int r0 = (warpM * 32 + mf * 16 + lq) * PADH;
        int r1 = (warpM * 32 + mf * 16 + 8 + lq) * PADH;
#pragma unroll
        for (int ks = 0; ks < 4; ks++) {
            int c0 = 8 * ks + lr, c1 = 8 * ks + 4 + lr;
            Ah[mf][ks][0] = Dh2[r0 + c0];
            Ah[mf][ks][1] = Dh2[r1 + c0];
            Ah[mf][ks][2] = Dh2[r0 + c1];
            Ah[mf][ks][3] = Dh2[r1 + c1];
            Al[mf][ks][0] = Dl2[r0 + c0];
            Al[mf][ks][1] = Dl2[r1 + c0];
            Al[mf][ks][2] = Dl2[r0 + c1];
            Al[mf][ks][3] = Dl2[r1 + c1];
        }
    }

    // ---- W prefetch (chunk 0 = level-1 cols [0,64))
    float4 wpref[6];
#pragma unroll
    for (int k = 0; k < 6; k++) {
        int idx = tid + k * 256;             // 0..1535
        int g   = idx >> 4;
        int j4  = (idx & 15) * 4;
        wpref[k] = *(const float4*)(Wih0 + (size_t)(gbase + g) * SIGW + 0 + j4);
    }

    float R[2][3][4];
#pragma unroll
    for (int mf = 0; mf < 2; mf++)
#pragma unroll
        for (int nf = 0; nf < 3; nf++)
#pragma unroll
            for (int q = 0; q < 4; q++) R[mf][nf][q] = 0.0f;

    for (int c = 0; c < 65; c++) {
        __syncthreads();                     // previous chunk's MMAs done with W smem
        // store prefetched W -> smem with bf16 hi/lo split
#pragma unroll
        for (int k = 0; k < 6; k++) {
            int idx = tid + k * 256;
            int g   = idx >> 4;
            int h2  = (idx & 15) * 2;        // half2 slot base
            float4 w = wpref[k];
            float hx = bf_hi(w.x), hy = bf_hi(w.y), hz = bf_hi(w.z), hw = bf_hi(w.w);
            Wh2[g * PADH + h2]     = bfpack(hx, hy);
            Wh2[g * PADH + h2 + 1] = bfpack(hz, hw);
            Wl2[g * PADH + h2]     = bfpack(w.x - hx, w.y - hy);
            Wl2[g * PADH + h2 + 1] = bfpack(w.z - hz, w.w - hw);
        }
        __syncthreads();

        // prefetch next chunk (cols 64 + c*64) — overlaps with MMAs below
        if (c < 64) {
            const int koff = CC + c * CC;
#pragma unroll
            for (int k = 0; k < 6; k++) {
                int idx = tid + k * 256;
                int g   = idx >> 4;
                int j4  = (idx & 15) * 4;
                wpref[k] = *(const float4*)(Wih0 + (size_t)(gbase + g) * SIGW + koff + j4);
            }
        }

        // Y = D . W_c^T   (bf16 3-product)
        float Y[2][3][4];
#pragma unroll
        for (int mf = 0; mf < 2; mf++)
#pragma unroll
            for (int nf = 0; nf < 3; nf++)
#pragma unroll
                for (int q = 0; q < 4; q++) Y[mf][nf][q] = 0.0f;

#pragma unroll
        for (int ks = 0; ks < 4; ks++) {
#pragma unroll
            for (int nf = 0; nf < 3; nf++) {
                int n0 = (warpN * 24 + nf * 8 + lq) * PADH;
                uint32_t b0h = Wh2[n0 + 8 * ks + lr];
                uint32_t b1h = Wh2[n0 + 8 * ks + 4 + lr];
                uint32_t b0l = Wl2[n0 + 8 * ks + lr];
                uint32_t b1l = Wl2[n0 + 8 * ks + 4 + lr];
#pragma unroll
                for (int mf = 0; mf < 2; mf++) {
                    MMA_BF16(Y[mf][nf][0], Y[mf][nf][1], Y[mf][nf][2], Y[mf][nf][3],
                             Ah[mf][ks][0], Ah[mf][ks][1], Ah[mf][ks][2], Ah[mf][ks][3],
                             b0h, b1h);
                    MMA_BF16(Y[mf][nf][0], Y[mf][nf][1], Y[mf][nf][2], Y[mf][nf][3],
                             Al[mf][ks][0], Al[mf][ks][1], Al[mf][ks][2], Al[mf][ks][3],
                             b0h, b1h);
                    MMA_BF16(Y[mf][nf][0], Y[mf][nf][1], Y[mf][nf][2], Y[mf][nf][3],
                             Ah[mf][ks][0], Ah[mf][ks][1], Ah[mf][ks][2], Ah[mf][ks][3],
                             b0l, b1l);
                }
            }
        }

        // R += diag(scale) . Y
#pragma unroll
        for (int mf = 0; mf < 2; mf++) {
            float av0 = 1.0f, av1 = 1.0f;
            if (c > 0) {
                int r0 = warpM * 32 + mf * 16 + lq;
                av0 = a_s[(c - 1) * 68 + r0];
                av1 = a_s[(c - 1) * 68 + r0 + 8];
            }
#pragma unroll
            for (int nf = 0; nf < 3; nf++) {
                R[mf][nf][0] = fmaf(av0, Y[mf][nf][0], R[mf][nf][0]);
                R[mf][nf][1] = fmaf(av0, Y[mf][nf][1], R[mf][nf][1]);
                R[mf][nf][2] = fmaf(av1, Y[mf][nf][2], R[mf][nf][2]);
                R[mf][nf][3] = fmaf(av1, Y[mf][nf][3], R[mf][nf][3]);
            }
        }
    }

    // ---- epilogue: c0,c1 at (row, 2lr..+1), c2,c3 at (row+8, ...)
#pragma unroll
    for (int mf = 0; mf < 2; mf++) {
        int trow = t0 + warpM * 32 + mf * 16 + lq;
#pragma unroll
        for (int nf = 0; nf < 3; nf++) {
            int g = gbase + warpN * 24 + nf * 8 + 2 * lr;
            float* rp0 = g_R + ((size_t)b * LL + trow) * GG + g;
            float* rp1 = g_R + ((size_t)b * LL + trow + 8) * GG + g;
            *(float2*)rp0 = make_float2(R[mf][nf][0], R[mf][nf][1]);
            *(float2*)rp1 = make_float2(R[mf][nf][2], R[mf][nf][3]);
        }
    }
}

// ---------------------------------------------------------------------------
// Fast activations
// ---------------------------------------------------------------------------
__device__ __forceinline__ float fast_sigm(float v) {
    return __fdividef(1.0f, 1.0f + __expf(-v));
}
__device__ __forceinline__ float fast_tanh(float v) {
    v = fminf(fmaxf(v, -10.0f), 10.0f);
    float e = __expf(2.0f * v);
    return __fdividef(e - 1.0f, e + 1.0f);
}

__device__ __forceinline__ float dot64(const float* __restrict__ w,
                                       const float* __restrict__ hs) {
    float s0 = 0.f, s1 = 0.f, s2 = 0.f, s3 = 0.f;
#pragma unroll
    for (int k = 0; k < HH; k += 4) {
        float4 h4 = *(const float4*)&hs[k];
        s0 = fmaf(w[k],     h4.x, s0);
        s1 = fmaf(w[k + 1], h4.y, s1);
        s2 = fmaf(w[k + 2], h4.z, s2);
        s3 = fmaf(w[k + 3], h4.w, s3);
    }
    return (s0 + s1) + (s2 + s3);
}

// ---------------------------------------------------------------------------
// Kernel C: fused 2-layer GRU, software-pipelined (layer 1 one step behind).
// 576 threads = 3 roles x 192 gates. One block per batch element.
// ---------------------------------------------------------------------------
__global__ void __launch_bounds__(3 * GG, 1) gru_fused_kernel(
    const float* __restrict__ Whh0, const float* __restrict__ bih0, const float* __restrict__ bhh0,
    const float* __restrict__ Wih1, const float* __restrict__ Whh1,
    const float* __restrict__ bih1, const float* __restrict__ bhh1,
    float* __restrict__ out)
{
    __shared__ float h0buf[2][HH];
    __shared__ float h1s[HH];
    __shared__ float s_xg0[GG], s_gh0[GG], s_xg1[GG], s_gh1[GG];

    const int b    = blockIdx.x;
    const int tid  = threadIdx.x;
    const int role = tid / GG;   // 0,1,2
    const int g    = tid - role * GG;

    const float* wsrc = (role == 0) ? Whh0 : (role == 1) ? Wih1 : Whh1;
    float wreg[HH];
#pragma unroll
    for (int k = 0; k < HH; k++) wreg[k] = wsrc[g * HH + k];

    const float bias = (role == 0) ? bhh0[g] : (role == 1) ? bih1[g] : bhh1[g];

    float acc = 0.0f, rv_next = 0.0f;
    const float* rptr = g_R + (size_t)b * LL * GG + g;
    if (role == 0) { acc = bih0[g]; rv_next = rptr[0]; }

    if (tid < HH) { h0buf[0][tid] = 0.0f; h0buf[1][tid] = 0.0f; h1s[tid] = 0.0f; }
    __syncthreads();

    for (int s = 0; s <= LL; s++) {
        const float* hprev0 = h0buf[(s + 1) & 1];   // h0[s-1]

        if (role == 0) {
            if (s < LL) {
                float rv = rv_next;
                if (s + 1 < LL) rv_next = rptr[(size_t)(s + 1) * GG];
                acc += rv;
                s_xg0[g] = acc;
                s_gh0[g] = bias + dot64(wreg, hprev0);
            }
        } else if (role == 1) {
            if (s >= 1) s_xg1[g] = bias + dot64(wreg, hprev0);
        } else {
            if (s >= 1) s_gh1[g] = bias + dot64(wreg, h1s);
        }
        __syncthreads();

        if (tid < HH) {
            if (s < LL) {
                float r = fast_sigm(s_xg0[tid] + s_gh0[tid]);
                float z = fast_sigm(s_xg0[HH + tid] + s_gh0[HH + tid]);
                float n = fast_tanh(s_xg0[2 * HH + tid] + r * s_gh0[2 * HH + tid]);
                h0buf[s & 1][tid] = (1.0f - z) * n + z * hprev0[tid];
            }
        } else if (tid >= GG && tid < GG + HH) {
            if (s >= 1) {
                int q = tid - GG;
                float r = fast_sigm(s_xg1[q] + s_gh1[q]);
                float z = fast_sigm(s_xg1[HH + q] + s_gh1[HH + q]);
                float n = fast_tanh(s_xg1[2 * HH + q] + r * s_gh1[2 * HH + q]);
                float hn = (1.0f - z) * n + z * h1s[q];
                h1s[q] = hn;
                out[((size_t)b * LL + (s - 1)) * HH + q] = hn;
            }
        }
        __syncthreads();
    }
}

// ---------------------------------------------------------------------------
extern "C" void kernel_launch(void* const* d_in, const int* in_sizes, int n_in,
                              void* d_out, int out_size)
{
    const float* x    = (const float*)d_in[0];
    const float* cw1  = (const float*)d_in[1];
    const float* cb1  = (const float*)d_in[2];
    const float* cw2  = (const float*)d_in[3];
    const float* cb2  = (const float*)d_in[4];
    const float* Wih0 = (const float*)d_in[5];
    const float* Whh0 = (const float*)d_in[6];
    const float* bih0 = (const float*)d_in[7];
    const float* bhh0 = (const float*)d_in[8];
    const float* Wih1 = (const float*)d_in[9];
    const float* Whh1 = (const float*)d_in[10];
    const float* bih1 = (const float*)d_in[11];
    const float* bhh1 = (const float*)d_in[12];
    float* out = (float*)d_out;

    // opt-in to >48KB dynamic smem (host attribute set, not an allocation)
    cudaFuncSetAttribute(siggemm_bf16_kernel,
                         cudaFuncAttributeMaxDynamicSharedMemorySize, SMEM_TC_BYTES);

    augment_kernel<<<BB, LL>>>(x, cw1, cb1, cw2, cb2);

    dim3 gridB(256, 2);
    siggemm_bf16_kernel<<<gridB, 256, SMEM_TC_BYTES>>>(Wih0);

    gru_fused_kernel<<<BB, 3 * GG>>>(Whh0, bih0, bhh0,
                                     Wih1, Whh1, bih1, bhh1, out);
}